// round 9
// baseline (speedup 1.0000x reference)
#include <cuda_runtime.h>

// SC-based GEMM, collapsed analytically:
//   out[m,n] = sum_k min(t1[m,k], t2[k,n]) * e1[m,k] * e2[k,n]
// t = floor(norm*256), e = sign * 2^{-s} (extra /256 folded into e2).
// Valid because rngSeq = arange(L) and the reference's ascending sequence
// are sorted unary prefixes, so popcount(b1 & b2) == min(t1, t2).
//
// SINGLE kernel: fused encode + split-K GEMM + stream-K fixup epilogue.
// Each split stores its partial; the last-arriving block per output tile
// (per-tile atomic counter) sums the 8 L2-hot partials and writes out,
// then resets the counter (deterministic across graph replays: the sum
// order is always split 0..7).

#define MKN 256
#define BM 64
#define BN 64
#define BK 32
#define KSPLIT 8         // 256 / BK
#define NTILE 16         // (256/BM) * (256/BN)

__device__ float gPart[KSPLIT * MKN * MKN];   // 2MB split-K partials
__device__ unsigned gCnt[NTILE];              // zero-init; reset each run

__device__ __forceinline__ float2 sc_encode(float x, int extra_shift) {
    if (x == 0.0f) return make_float2(0.0f, 0.0f);
    float ax = fabsf(x);
    int bits = __float_as_int(ax);
    int q = (bits >> 23) - 126;               // frexp exponent (normals)
    int s = ((bits & 0x7FFFFF) == 0) ? (1 - q) : (-q);   // floor(-log2 ax)
    s = max(0, min(s, 8));                    // clip to DATA_WIDTH
    // thr = floor(ax * 2^s * 256); power-of-2 scale is exact
    float thr = floorf(ax * __int_as_float((127 + s + 8) << 23));
    // e = sign(x) * 2^{-s-extra}: build bits directly
    float e = __int_as_float(((127 - s - extra_shift) << 23) |
                             (__float_as_int(x) & 0x80000000));
    return make_float2(thr, e);
}

__global__ __launch_bounds__(256)
void sc_gemm_kernel(const float* __restrict__ A,
                    const float* __restrict__ B,
                    float* __restrict__ out) {
    __shared__ float sAt[BK][BM], sAe[BK][BM];    // [k][m], 8KB each
    __shared__ float sBt[BK][BN], sBe[BK][BN];    // [k][n], 8KB each
    __shared__ unsigned sLast;

    const int t  = threadIdx.x;
    const int tx = t & 15;                    // n-group
    const int ty = t >> 4;                    // m-group
    const int m0 = blockIdx.y * BM;
    const int n0 = blockIdx.x * BN;
    const int k0 = blockIdx.z * BK;
    const int tile = blockIdx.y * 4 + blockIdx.x;

    // ---- Encode A tile [BM x BK] into transposed SoA smem.
    {
        int m  = t & 63;
        int kg = t >> 6;                      // 0..3
        const float* src = A + (m0 + m) * MKN + k0 + kg * 8;
        float4 v0 = *(const float4*)src;
        float4 v1 = *(const float4*)(src + 4);
        float vv[8] = {v0.x, v0.y, v0.z, v0.w, v1.x, v1.y, v1.z, v1.w};
        #pragma unroll
        for (int j = 0; j < 8; ++j) {
            float2 en = sc_encode(vv[j], 0);
            sAt[kg * 8 + j][m] = en.x;
            sAe[kg * 8 + j][m] = en.y;
        }
    }
    // ---- Encode B tile [BK x BN]: coalesced scalar loads, consecutive STS.
    {
        #pragma unroll
        for (int j = 0; j < 8; ++j) {
            int i = t + j * 256;
            int k = i >> 6;                   // 0..31
            int n = i & 63;
            float2 en = sc_encode(B[(k0 + k) * MKN + n0 + n], 8);
            sBt[k][n] = en.x;
            sBe[k][n] = en.y;
        }
    }
    __syncthreads();

    float acc[4][4];
    #pragma unroll
    for (int i = 0; i < 4; ++i)
        #pragma unroll
        for (int j = 0; j < 4; ++j) acc[i][j] = 0.0f;

    #pragma unroll 8
    for (int k = 0; k < BK; ++k) {
        float4 at = *(const float4*)&sAt[k][ty * 4];   // 2-addr broadcast
        float4 ae = *(const float4*)&sAe[k][ty * 4];
        float4 bt = *(const float4*)&sBt[k][tx * 4];   // 16B-stride
        float4 be = *(const float4*)&sBe[k][tx * 4];
        const float* atp = &at.x; const float* aep = &ae.x;
        const float* btp = &bt.x; const float* bep = &be.x;
        #pragma unroll
        for (int i = 0; i < 4; ++i)
            #pragma unroll
            for (int j = 0; j < 4; ++j)
                acc[i][j] = fmaf(fminf(atp[i], btp[j]) * aep[i], bep[j],
                                 acc[i][j]);
    }

    // ---- Store this split's partial (plain vector stores, no atomics).
    float* part = gPart + blockIdx.z * (MKN * MKN);
    #pragma unroll
    for (int i = 0; i < 4; ++i) {
        int m = m0 + ty * 4 + i;
        *(float4*)&part[m * MKN + n0 + tx * 4] =
            make_float4(acc[i][0], acc[i][1], acc[i][2], acc[i][3]);
    }

    // ---- Stream-K fixup: last block to finish this (m,n) tile reduces it.
    __threadfence();                          // publish partials
    __syncthreads();                          // all stores issued
    if (t == 0)
        sLast = atomicAdd(&gCnt[tile], 1u);   // device-scope RMW
    __syncthreads();
    if (sLast == KSPLIT - 1) {
        __threadfence();                      // acquire side
        #pragma unroll
        for (int j = 0; j < 16; ++j) {
            int idx = t + j * 256;            // 0..4095 within tile
            int m = m0 + (idx >> 6);
            int n = n0 + (idx & 63);
            int g = m * MKN + n;
            float s0 = gPart[g]                   + gPart[1 * MKN * MKN + g];
            float s1 = gPart[2 * MKN * MKN + g]   + gPart[3 * MKN * MKN + g];
            float s2 = gPart[4 * MKN * MKN + g]   + gPart[5 * MKN * MKN + g];
            float s3 = gPart[6 * MKN * MKN + g]   + gPart[7 * MKN * MKN + g];
            out[g] = (s0 + s1) + (s2 + s3);
        }
        if (t == 0) gCnt[tile] = 0;           // reset for next graph replay
    }
}

extern "C" void kernel_launch(void* const* d_in, const int* in_sizes, int n_in,
                              void* d_out, int out_size) {
    const float* A = (const float*)d_in[0];   // tensor_1 [256,256]
    const float* B = (const float*)d_in[1];   // tensor_2 [256,256]
    // d_in[2] = rngSeq (arange(256)); sortedness folded into the math.
    float* out = (float*)d_out;

    dim3 grid(MKN / BN, MKN / BM, KSPLIT);    // 4 x 4 x 8 = 128 blocks
    sc_gemm_kernel<<<grid, 256>>>(A, B, out);
}

// round 10
// speedup vs baseline: 1.3175x; 1.3175x over previous
#include <cuda_runtime.h>
#include <cooperative_groups.h>

namespace cg = cooperative_groups;

// SC-based GEMM, collapsed analytically:
//   out[m,n] = sum_k min(t1[m,k], t2[k,n]) * e1[m,k] * e2[k,n]
// t = floor(norm*256), e = sign * 2^{-s} (extra /256 folded into e2).
// Valid because rngSeq = arange(L) and the reference's ascending sequence
// are sorted unary prefixes, so popcount(b1 & b2) == min(t1, t2).
//
// SINGLE kernel, cluster-8 split-K: the 8 k-splits of each 64x64 output
// tile form one cluster. Partials live in per-CTA shared memory and are
// reduced over DSMEM after cluster.sync() — no global partials, no
// atomics, no device-scope fences. 128 CTAs = one wave.

#define MKN 256
#define BM 64
#define BN 64
#define BK 32
#define KSPLIT 8         // 256 / BK = cluster size

__device__ __forceinline__ float2 sc_encode(float x, int extra_shift) {
    if (x == 0.0f) return make_float2(0.0f, 0.0f);
    float ax = fabsf(x);
    int bits = __float_as_int(ax);
    int q = (bits >> 23) - 126;               // frexp exponent (normals)
    int s = ((bits & 0x7FFFFF) == 0) ? (1 - q) : (-q);   // floor(-log2 ax)
    s = max(0, min(s, 8));                    // clip to DATA_WIDTH
    // thr = floor(ax * 2^s * 256); power-of-2 scale is exact
    float thr = floorf(ax * __int_as_float((127 + s + 8) << 23));
    // e = sign(x) * 2^{-s-extra}: build bits directly
    float e = __int_as_float(((127 - s - extra_shift) << 23) |
                             (__float_as_int(x) & 0x80000000));
    return make_float2(thr, e);
}

__global__ __launch_bounds__(256) __cluster_dims__(1, 1, 8)
void sc_gemm_kernel(const float* __restrict__ A,
                    const float* __restrict__ B,
                    float* __restrict__ out) {
    __shared__ float sAt[BK][BM], sAe[BK][BM];    // [k][m], 8KB each
    __shared__ float sBt[BK][BN], sBe[BK][BN];    // [k][n], 8KB each
    __shared__ float sP[BM * BN];                 // 16KB partial tile

    cg::cluster_group cluster = cg::this_cluster();

    const int t  = threadIdx.x;
    const int tx = t & 15;                    // n-group
    const int ty = t >> 4;                    // m-group
    const int m0 = blockIdx.y * BM;
    const int n0 = blockIdx.x * BN;
    const int rank = blockIdx.z;              // split index == cluster rank
    const int k0 = rank * BK;

    // ---- Encode A tile [BM x BK] into transposed SoA smem.
    {
        int m  = t & 63;
        int kg = t >> 6;                      // 0..3
        const float* src = A + (m0 + m) * MKN + k0 + kg * 8;
        float4 v0 = *(const float4*)src;
        float4 v1 = *(const float4*)(src + 4);
        float vv[8] = {v0.x, v0.y, v0.z, v0.w, v1.x, v1.y, v1.z, v1.w};
        #pragma unroll
        for (int j = 0; j < 8; ++j) {
            float2 en = sc_encode(vv[j], 0);
            sAt[kg * 8 + j][m] = en.x;
            sAe[kg * 8 + j][m] = en.y;
        }
    }
    // ---- Encode B tile [BK x BN]: coalesced scalar loads, consecutive STS.
    {
        #pragma unroll
        for (int j = 0; j < 8; ++j) {
            int i = t + j * 256;
            int k = i >> 6;                   // 0..31
            int n = i & 63;
            float2 en = sc_encode(B[(k0 + k) * MKN + n0 + n], 8);
            sBt[k][n] = en.x;
            sBe[k][n] = en.y;
        }
    }
    __syncthreads();

    float acc[4][4];
    #pragma unroll
    for (int i = 0; i < 4; ++i)
        #pragma unroll
        for (int j = 0; j < 4; ++j) acc[i][j] = 0.0f;

    #pragma unroll 8
    for (int k = 0; k < BK; ++k) {
        float4 at = *(const float4*)&sAt[k][ty * 4];   // 2-addr broadcast
        float4 ae = *(const float4*)&sAe[k][ty * 4];
        float4 bt = *(const float4*)&sBt[k][tx * 4];   // 16B-stride
        float4 be = *(const float4*)&sBe[k][tx * 4];
        const float* atp = &at.x; const float* aep = &ae.x;
        const float* btp = &bt.x; const float* bep = &be.x;
        #pragma unroll
        for (int i = 0; i < 4; ++i)
            #pragma unroll
            for (int j = 0; j < 4; ++j)
                acc[i][j] = fmaf(fminf(atp[i], btp[j]) * aep[i], bep[j],
                                 acc[i][j]);
    }

    // ---- Stash this split's partial in OUR shared memory (no globals).
    #pragma unroll
    for (int i = 0; i < 4; ++i)
        *(float4*)&sP[(ty * 4 + i) * BN + tx * 4] =
            make_float4(acc[i][0], acc[i][1], acc[i][2], acc[i][3]);

    // ---- Cluster barrier: all 8 splits' partials are now readable.
    cluster.sync();

    // ---- Each rank reduces a 512-float slice across all 8 ranks (DSMEM),
    //      fixed rank order 0..7 -> deterministic.
    {
        int o = rank * (BM * BN / KSPLIT) + t * 2;    // this thread's 2 outs
        float2 s = make_float2(0.0f, 0.0f);
        #pragma unroll
        for (int r = 0; r < KSPLIT; ++r) {
            const float2* p = (const float2*)cluster.map_shared_rank(sP, r);
            float2 v = p[o >> 1];
            s.x += v.x;
            s.y += v.y;
        }
        int m = m0 + (o >> 6);
        int n = n0 + (o & 63);
        *(float2*)&out[m * MKN + n] = s;
    }

    // ---- No CTA may exit while peers still read its smem.
    cluster.sync();
}

extern "C" void kernel_launch(void* const* d_in, const int* in_sizes, int n_in,
                              void* d_out, int out_size) {
    const float* A = (const float*)d_in[0];   // tensor_1 [256,256]
    const float* B = (const float*)d_in[1];   // tensor_2 [256,256]
    // d_in[2] = rngSeq (arange(256)); sortedness folded into the math.
    float* out = (float*)d_out;

    dim3 grid(MKN / BN, MKN / BM, KSPLIT);    // 4 x 4 x 8 = 128 blocks
    sc_gemm_kernel<<<grid, 256>>>(A, B, out);
}

// round 11
// speedup vs baseline: 1.5731x; 1.1940x over previous
#include <cuda_runtime.h>

// SC-based GEMM, collapsed analytically:
//   out[m,n] = sum_k min(t1[m,k], t2[k,n]) * e1[m,k] * e2[k,n]
// t = floor(norm*256), e = sign * 2^{-s} (extra /256 folded into e2).
// Valid because rngSeq = arange(L) and the reference's ascending sequence
// are sorted unary prefixes, so popcount(b1 & b2) == min(t1, t2).
//
// Fused encode+GEMM (split-K partials, plain stores) + scalar reduce.
// The reduce is a PDL (programmatic dependent launch) so its launch ramp
// overlaps the GEMM; it gates on cudaGridDependencySynchronize() before
// reading the partials.

#define MKN 256
#define BM 64
#define BN 64
#define BK 32
#define KSPLIT 8         // 256 / BK

__device__ float gPart[KSPLIT * MKN * MKN];   // 2MB split-K partials

__device__ __forceinline__ float2 sc_encode(float x, int extra_shift) {
    if (x == 0.0f) return make_float2(0.0f, 0.0f);
    float ax = fabsf(x);
    int bits = __float_as_int(ax);
    int q = (bits >> 23) - 126;               // frexp exponent (normals)
    int s = ((bits & 0x7FFFFF) == 0) ? (1 - q) : (-q);   // floor(-log2 ax)
    s = max(0, min(s, 8));                    // clip to DATA_WIDTH
    // thr = floor(ax * 2^s * 256); power-of-2 scale is exact
    float thr = floorf(ax * __int_as_float((127 + s + 8) << 23));
    // e = sign(x) * 2^{-s-extra}: build bits directly
    float e = __int_as_float(((127 - s - extra_shift) << 23) |
                             (__float_as_int(x) & 0x80000000));
    return make_float2(thr, e);
}

__global__ __launch_bounds__(256)
void sc_gemm_kernel(const float* __restrict__ A,
                    const float* __restrict__ B) {
    __shared__ float sAt[BK][BM], sAe[BK][BM];    // [k][m], 8KB each
    __shared__ float sBt[BK][BN], sBe[BK][BN];    // [k][n], 8KB each

    const int t  = threadIdx.x;
    const int tx = t & 15;                    // n-group
    const int ty = t >> 4;                    // m-group
    const int m0 = blockIdx.y * BM;
    const int n0 = blockIdx.x * BN;
    const int k0 = blockIdx.z * BK;

    // ---- Encode A tile [BM x BK] into transposed SoA smem.
    {
        int m  = t & 63;
        int kg = t >> 6;                      // 0..3
        const float* src = A + (m0 + m) * MKN + k0 + kg * 8;
        float4 v0 = *(const float4*)src;
        float4 v1 = *(const float4*)(src + 4);
        float vv[8] = {v0.x, v0.y, v0.z, v0.w, v1.x, v1.y, v1.z, v1.w};
        #pragma unroll
        for (int j = 0; j < 8; ++j) {
            float2 en = sc_encode(vv[j], 0);
            sAt[kg * 8 + j][m] = en.x;
            sAe[kg * 8 + j][m] = en.y;
        }
    }
    // ---- Encode B tile [BK x BN]: coalesced scalar loads, consecutive STS.
    {
        #pragma unroll
        for (int j = 0; j < 8; ++j) {
            int i = t + j * 256;
            int k = i >> 6;                   // 0..31
            int n = i & 63;
            float2 en = sc_encode(B[(k0 + k) * MKN + n0 + n], 8);
            sBt[k][n] = en.x;
            sBe[k][n] = en.y;
        }
    }
    __syncthreads();

    float acc[4][4];
    #pragma unroll
    for (int i = 0; i < 4; ++i)
        #pragma unroll
        for (int j = 0; j < 4; ++j) acc[i][j] = 0.0f;

    #pragma unroll 8
    for (int k = 0; k < BK; ++k) {
        float4 at = *(const float4*)&sAt[k][ty * 4];   // 2-addr broadcast
        float4 ae = *(const float4*)&sAe[k][ty * 4];
        float4 bt = *(const float4*)&sBt[k][tx * 4];   // 16B-stride
        float4 be = *(const float4*)&sBe[k][tx * 4];
        const float* atp = &at.x; const float* aep = &ae.x;
        const float* btp = &bt.x; const float* bep = &be.x;
        #pragma unroll
        for (int i = 0; i < 4; ++i)
            #pragma unroll
            for (int j = 0; j < 4; ++j)
                acc[i][j] = fmaf(fminf(atp[i], btp[j]) * aep[i], bep[j],
                                 acc[i][j]);
    }

    // ---- Plain vector stores of the split-K partial (no atomics).
    float* part = gPart + blockIdx.z * (MKN * MKN);
    #pragma unroll
    for (int i = 0; i < 4; ++i) {
        int m = m0 + ty * 4 + i;
        *(float4*)&part[m * MKN + n0 + tx * 4] =
            make_float4(acc[i][0], acc[i][1], acc[i][2], acc[i][3]);
    }

    // Let the dependent reduce kernel begin its launch/ramp now; its
    // cudaGridDependencySynchronize() still waits for our completion.
    cudaTriggerProgrammaticLaunchCompletion();
}

__global__ __launch_bounds__(256)
void sc_reduce_kernel(float* __restrict__ out) {
    int i = blockIdx.x * 256 + threadIdx.x;   // prologue before the gate
    cudaGridDependencySynchronize();          // wait for GEMM's memory
    float s0 = gPart[i]                 + gPart[1 * MKN * MKN + i];
    float s1 = gPart[2 * MKN * MKN + i] + gPart[3 * MKN * MKN + i];
    float s2 = gPart[4 * MKN * MKN + i] + gPart[5 * MKN * MKN + i];
    float s3 = gPart[6 * MKN * MKN + i] + gPart[7 * MKN * MKN + i];
    out[i] = (s0 + s1) + (s2 + s3);
}

extern "C" void kernel_launch(void* const* d_in, const int* in_sizes, int n_in,
                              void* d_out, int out_size) {
    const float* A = (const float*)d_in[0];   // tensor_1 [256,256]
    const float* B = (const float*)d_in[1];   // tensor_2 [256,256]
    // d_in[2] = rngSeq (arange(256)); sortedness folded into the math.
    float* out = (float*)d_out;

    dim3 grid(MKN / BN, MKN / BM, KSPLIT);    // 4 x 4 x 8 = 128 blocks
    sc_gemm_kernel<<<grid, 256>>>(A, B);

    // Dependent launch: overlap the reduce's launch ramp with the GEMM.
    cudaLaunchConfig_t cfg = {};
    cfg.gridDim  = dim3(MKN * MKN / 256);     // 256 blocks
    cfg.blockDim = dim3(256);
    cfg.stream   = 0;                         // same (captured) stream
    cudaLaunchAttribute attr[1];
    attr[0].id = cudaLaunchAttributeProgrammaticStreamSerialization;
    attr[0].val.programmaticStreamSerializationAllowed = 1;
    cfg.attrs = attr;
    cfg.numAttrs = 1;
    cudaLaunchKernelEx(&cfg, sc_reduce_kernel, out);
}